// round 3
// baseline (speedup 1.0000x reference)
#include <cuda_runtime.h>
#include <cuda_bf16.h>

// TGSM fused kernel v3: one WARP handles TWO batches (lanes 0-15 / 16-31).
// B=1024, T=256, N=14, Fd=4, H=32, K=5, C=2

#define Bn 1024
#define Tn 256
#define Nn 14
#define Hn 32

__device__ __forceinline__ float warp_sum(float v) {
    v += __shfl_xor_sync(0xffffffffu, v, 16);
    v += __shfl_xor_sync(0xffffffffu, v, 8);
    v += __shfl_xor_sync(0xffffffffu, v, 4);
    v += __shfl_xor_sync(0xffffffffu, v, 2);
    v += __shfl_xor_sync(0xffffffffu, v, 1);
    return v;
}

__device__ __forceinline__ float elu(float y) {
    return (y > 0.0f) ? y : (__expf(y) - 1.0f);
}

__global__ __launch_bounds__(32)
void tgsm_kernel(const float* __restrict__ ws,
                 const float* __restrict__ gate_w, const float* __restrict__ gate_b,
                 const float* __restrict__ gcn_w,  const float* __restrict__ gcn_b,
                 const float* __restrict__ ln_g,   const float* __restrict__ ln_b,
                 const float* __restrict__ attn_w, const float* __restrict__ attn_b,
                 const float* __restrict__ c1_w,   const float* __restrict__ c1_b,
                 const float* __restrict__ c2_w,   const float* __restrict__ c2_b,
                 const float* __restrict__ c3_w,   const float* __restrict__ c3_b,
                 float* __restrict__ out)
{
    const int b0   = blockIdx.x * 2;          // batch for half 0
    const int lane = threadIdx.x;             // 0..31
    const int half = lane >> 4;               // 0 or 1 -> which batch
    const int hl   = lane & 15;               // node index within half
    const int hb   = half * 17;               // padded base for float4/float2 arrays
    const int bb   = b0 + half;               // this lane's batch

    __shared__ float4 s_nrm[34];
    __shared__ float4 s_q[34];
    __shared__ float4 s_xp[34];
    __shared__ float2 s_mr[34];
    __shared__ float  s_dis[32];
    __shared__ float  s_esm[2][201];
    __shared__ float  s_comb[2][40];
    __shared__ float  s_b1[2][64];

    // ---- per-lane constants (lane == H channel) ----
    float Wc0 = gcn_w[0 * Hn + lane];
    float Wc1 = gcn_w[1 * Hn + lane];
    float Wc2 = gcn_w[2 * Hn + lane];
    float Wc3 = gcn_w[3 * Hn + lane];
    float gcnb = gcn_b[lane];
    float lng  = ln_g[lane];
    float lnb  = ln_b[lane];
    float awv  = attn_w[lane];
    float gw0  = gate_w[0];
    float gw1  = gate_w[1];
    float gbv  = gate_b[0];
    float attnb = attn_b[0];

    // ---- closed-form LN statistics precompute ----
    float SW0 = warp_sum(Wc0);
    float SW1 = warp_sum(Wc1);
    float SW2 = warp_sum(Wc2);
    float SW3 = warp_sum(Wc3);
    float Sb  = warp_sum(gcnb);
    float vW[5] = {Wc0, Wc1, Wc2, Wc3, gcnb};
    float G[5][5];
    #pragma unroll
    for (int i = 0; i < 5; i++) {
        #pragma unroll
        for (int j = i; j < 5; j++) {
            float g = warp_sum(vW[i] * vW[j]);
            G[i][j] = g; G[j][i] = g;
        }
    }

    // esm column `hl` of this half's batch lives in registers (symmetric)
    float e[Nn];
    #pragma unroll
    for (int i = 0; i < Nn; i++) e[i] = 0.0f;

    // online-softmax states for both batches (lane == H channel)
    float P0 = 0.0f, M0 = -1e30f, S0 = 0.0f;
    float P1 = 0.0f, M1 = -1e30f, S1 = 0.0f;

    const float4* src = reinterpret_cast<const float4*>(ws) + (size_t)bb * Tn * Nn;
    float4 dnext = make_float4(0.f, 0.f, 0.f, 0.f);
    if (hl < Nn) dnext = src[hl];

    for (int t = 0; t < Tn; t++) {
        // ---- phase 1: normalize de, stage nrm; prefetch next ----
        float4 de = dnext;
        float d2  = de.x*de.x + de.y*de.y + de.z*de.z + de.w*de.w;
        float inv = rsqrtf(fmaxf(d2, 1e-24f));
        float4 nrm = make_float4(de.x*inv, de.y*inv, de.z*inv, de.w*inv);
        if (hl < Nn) {
            s_nrm[hb + hl] = nrm;
            if (t + 1 < Tn) dnext = src[(t + 1) * Nn + hl];
        }
        __syncwarp();

        // ---- phase 2: adjacency + gate + esm update + rowsum (lane = column hl) ----
        float rowsum = 1.0f;
        #pragma unroll
        for (int n = 0; n < Nn; n++) {
            float4 nn4 = s_nrm[hb + n];
            float dot = nrm.x*nn4.x;
            dot = fmaf(nrm.y, nn4.y, dot);
            dot = fmaf(nrm.z, nn4.z, dot);
            dot = fmaf(nrm.w, nn4.w, dot);
            float adj = fmaf(dot, 0.5f, 0.5f);
            adj = (n == hl) ? 0.0f : adj;
            float ee = e[n];
            float x  = fmaf(gw0, ee, fmaf(gw1, adj, gbv));
            float z  = __fdividef(1.0f, 1.0f + __expf(-x));
            ee = fmaf(z, adj - ee, ee);
            e[n] = ee;
            rowsum += ee;
        }
        float dis = rsqrtf(fmaxf(rowsum, 1e-6f));
        if (hl < Nn) {
            s_q[hb + hl]        = make_float4(de.x*dis, de.y*dis, de.z*dis, de.w*dis);
            s_dis[half*16 + hl] = dis;
        }
        __syncwarp();

        // ---- phase 3: p = esm @ q, r = rowsum(a_norm); LN stats closed-form ----
        float4 p = make_float4(0.f, 0.f, 0.f, 0.f);
        float racc = 0.0f;
        #pragma unroll
        for (int m = 0; m < Nn; m++) {
            float4 qm = s_q[hb + m];
            float dm  = s_dis[half*16 + m];
            float em  = e[m];
            p.x = fmaf(em, qm.x, p.x);
            p.y = fmaf(em, qm.y, p.y);
            p.z = fmaf(em, qm.z, p.z);
            p.w = fmaf(em, qm.w, p.w);
            racc = fmaf(em, dm, racc);
        }
        if (hl < Nn) {
            float rr = dis * (racc + dis);
            float x0 = fmaf(de.x, dis, p.x) * dis;
            float x1 = fmaf(de.y, dis, p.y) * dis;
            float x2 = fmaf(de.z, dis, p.z) * dis;
            float x3 = fmaf(de.w, dis, p.w) * dis;
            float mu = (x0*SW0 + x1*SW1 + x2*SW2 + x3*SW3 + rr*Sb) * (1.0f/32.0f);
            float xt[5] = {x0, x1, x2, x3, rr};
            float s2 = 0.0f;
            #pragma unroll
            for (int i = 0; i < 5; i++) {
                float rowd = 0.0f;
                #pragma unroll
                for (int j = 0; j < 5; j++) rowd = fmaf(G[i][j], xt[j], rowd);
                s2 = fmaf(xt[i], rowd, s2);
            }
            s2 *= (1.0f/32.0f);
            float var  = fmaf(-mu, mu, s2);
            float istd = rsqrtf(var + 1e-5f);
            s_xp[hb + hl] = make_float4(x0*istd, x1*istd, x2*istd, x3*istd);
            s_mr[hb + hl] = make_float2(rr*istd, mu*istd);
        }
        __syncwarp();

        // ---- phase 5: LN apply + ELU + node mean, BOTH batches (lane = channel) ----
        float ge0 = 0.0f, ge1 = 0.0f;
        #pragma unroll
        for (int n = 0; n < Nn; n++) {
            float4 xa = s_xp[n];       float2 ma = s_mr[n];
            float4 xb = s_xp[17 + n];  float2 mb = s_mr[17 + n];
            float ha = -ma.y;
            ha = fmaf(xa.x, Wc0, ha); ha = fmaf(xa.y, Wc1, ha);
            ha = fmaf(xa.z, Wc2, ha); ha = fmaf(xa.w, Wc3, ha);
            ha = fmaf(ma.x, gcnb, ha);
            ge0 += elu(fmaf(ha, lng, lnb));
            float hbv = -mb.y;
            hbv = fmaf(xb.x, Wc0, hbv); hbv = fmaf(xb.y, Wc1, hbv);
            hbv = fmaf(xb.z, Wc2, hbv); hbv = fmaf(xb.w, Wc3, hbv);
            hbv = fmaf(mb.x, gcnb, hbv);
            ge1 += elu(fmaf(hbv, lng, lnb));
        }
        ge0 *= (1.0f / 14.0f);
        ge1 *= (1.0f / 14.0f);

        // ---- online softmax attention pooling, both batches ----
        float sc0 = warp_sum(ge0 * awv) + attnb;
        float sc1 = warp_sum(ge1 * awv) + attnb;
        {
            float nM = fmaxf(M0, sc0);
            float al = __expf(M0 - nM);
            float wt = __expf(sc0 - nM);
            P0 = fmaf(P0, al, wt * ge0);
            S0 = fmaf(S0, al, wt);
            M0 = nM;
        }
        {
            float nM = fmaxf(M1, sc1);
            float al = __expf(M1 - nM);
            float wt = __expf(sc1 - nM);
            P1 = fmaf(P1, al, wt * ge1);
            S1 = fmaf(S1, al, wt);
            M1 = nM;
        }
    }

    // ---- dump esm to shared (per half) ----
    if (hl < Nn) {
        #pragma unroll
        for (int n = 0; n < Nn; n++) s_esm[half][n * Nn + hl] = e[n];
    }
    __syncwarp();

    // ---- branchless cyclic Jacobi, both halves in lockstep ----
    float* base = s_esm[half];
    for (int sweep = 0; sweep < 8; sweep++) {
        for (int pp = 0; pp < Nn - 1; pp++) {
            for (int qq = pp + 1; qq < Nn; qq++) {
                float apq = base[pp * Nn + qq];
                float app = base[pp * Nn + pp];
                float aqq = base[qq * Nn + qq];
                float ap  = fabsf(apq);
                float den = (ap > 1e-20f) ? apq : 1e-20f;
                float theta = __fdividef(0.5f * (aqq - app), den);
                float tt = __fdividef(1.0f, fabsf(theta) + sqrtf(fmaf(theta, theta, 1.0f)));
                tt = (theta < 0.0f) ? -tt : tt;
                tt = (ap > 1e-20f) ? tt : 0.0f;        // identity rotation if apq~0
                float cc  = rsqrtf(fmaf(tt, tt, 1.0f));
                float ssn = tt * cc;
                int k = hl;
                bool act = (k < Nn) && (k != pp) && (k != qq);
                float akp = 0.f, akq = 0.f;
                if (act) { akp = base[k * Nn + pp]; akq = base[k * Nn + qq]; }
                __syncwarp();
                if (act) {
                    float nkp = fmaf(cc, akp, -ssn * akq);
                    float nkq = fmaf(ssn, akp,  cc * akq);
                    base[k * Nn + pp] = nkp; base[pp * Nn + k] = nkp;
                    base[k * Nn + qq] = nkq; base[qq * Nn + k] = nkq;
                }
                if (hl == pp) {
                    base[pp * Nn + pp] = fmaf(-tt, apq, app);
                    base[qq * Nn + qq] = fmaf( tt, apq, aqq);
                    base[pp * Nn + qq] = 0.0f;
                    base[qq * Nn + pp] = 0.0f;
                }
                __syncwarp();
            }
        }
    }

    // ---- top-5 eigenvalues via parallel rank (ascending) ----
    {
        float ev = (hl < Nn) ? base[hl * Nn + hl] : 1e30f;
        int rank = 0;
        #pragma unroll
        for (int j = 0; j < Nn; j++) {
            float evj = base[j * Nn + j];
            rank += (evj < ev || (evj == ev && j < hl)) ? 1 : 0;
        }
        if (hl < Nn && rank >= Nn - 5) s_comb[half][rank - (Nn - 5)] = ev;
    }
    // pooled attention outputs (all lanes hold both batches' channel values)
    s_comb[0][5 + lane] = __fdividef(P0, S0);
    s_comb[1][5 + lane] = __fdividef(P1, S1);
    __syncwarp();

    // ---- classifier: 37 -> 64 (elu) -> 32 (elu) -> 2, both batches ----
    {
        float a00 = c1_b[lane], a01 = c1_b[lane + 32];
        float a10 = a00,        a11 = a01;
        #pragma unroll
        for (int i = 0; i < 37; i++) {
            float w0 = c1_w[i * 64 + lane];
            float w1 = c1_w[i * 64 + 32 + lane];
            float ci0 = s_comb[0][i];
            float ci1 = s_comb[1][i];
            a00 = fmaf(ci0, w0, a00); a01 = fmaf(ci0, w1, a01);
            a10 = fmaf(ci1, w0, a10); a11 = fmaf(ci1, w1, a11);
        }
        s_b1[0][lane] = elu(a00); s_b1[0][lane + 32] = elu(a01);
        s_b1[1][lane] = elu(a10); s_b1[1][lane + 32] = elu(a11);
    }
    __syncwarp();
    {
        float b20 = c2_b[lane], b21 = b20;
        #pragma unroll
        for (int i = 0; i < 64; i++) {
            float w = c2_w[i * 32 + lane];
            b20 = fmaf(s_b1[0][i], w, b20);
            b21 = fmaf(s_b1[1][i], w, b21);
        }
        float h20 = elu(b20), h21 = elu(b21);
        float w30 = c3_w[lane * 2 + 0];
        float w31 = c3_w[lane * 2 + 1];
        float r00 = warp_sum(h20 * w30);
        float r01 = warp_sum(h20 * w31);
        float r10 = warp_sum(h21 * w30);
        float r11 = warp_sum(h21 * w31);
        if (lane == 0) {
            out[b0 * 2 + 0] = r00 + c3_b[0];
            out[b0 * 2 + 1] = r01 + c3_b[1];
            out[b0 * 2 + 2] = r10 + c3_b[0];
            out[b0 * 2 + 3] = r11 + c3_b[1];
        }
    }
}

extern "C" void kernel_launch(void* const* d_in, const int* in_sizes, int n_in,
                              void* d_out, int out_size)
{
    const float* ws     = (const float*)d_in[0];
    const float* gate_w = (const float*)d_in[1];
    const float* gate_b = (const float*)d_in[2];
    const float* gcn_w  = (const float*)d_in[3];
    const float* gcn_b  = (const float*)d_in[4];
    const float* ln_g   = (const float*)d_in[5];
    const float* ln_b   = (const float*)d_in[6];
    const float* attn_w = (const float*)d_in[7];
    const float* attn_b = (const float*)d_in[8];
    const float* c1_w   = (const float*)d_in[9];
    const float* c1_b   = (const float*)d_in[10];
    const float* c2_w   = (const float*)d_in[11];
    const float* c2_b   = (const float*)d_in[12];
    const float* c3_w   = (const float*)d_in[13];
    const float* c3_b   = (const float*)d_in[14];
    float* out = (float*)d_out;

    tgsm_kernel<<<Bn / 2, 32>>>(ws, gate_w, gate_b, gcn_w, gcn_b, ln_g, ln_b,
                                attn_w, attn_b, c1_w, c1_b, c2_w, c2_b,
                                c3_w, c3_b, out);
}

// round 4
// speedup vs baseline: 1.2250x; 1.2250x over previous
#include <cuda_runtime.h>
#include <cuda_bf16.h>

// TGSM fused kernel v4: one WARP per batch, software-pipelined across t.
// B=1024, T=256, N=14, Fd=4, H=32, K=5, C=2

#define Bn 1024
#define Tn 256
#define Nn 14
#define Hn 32

__device__ __forceinline__ float warp_sum(float v) {
    v += __shfl_xor_sync(0xffffffffu, v, 16);
    v += __shfl_xor_sync(0xffffffffu, v, 8);
    v += __shfl_xor_sync(0xffffffffu, v, 4);
    v += __shfl_xor_sync(0xffffffffu, v, 2);
    v += __shfl_xor_sync(0xffffffffu, v, 1);
    return v;
}

__device__ __forceinline__ float elu(float y) {
    return (y > 0.0f) ? y : (__expf(y) - 1.0f);
}

__global__ __launch_bounds__(32)
void tgsm_kernel(const float* __restrict__ ws,
                 const float* __restrict__ gate_w, const float* __restrict__ gate_b,
                 const float* __restrict__ gcn_w,  const float* __restrict__ gcn_b,
                 const float* __restrict__ ln_g,   const float* __restrict__ ln_b,
                 const float* __restrict__ attn_w, const float* __restrict__ attn_b,
                 const float* __restrict__ c1_w,   const float* __restrict__ c1_b,
                 const float* __restrict__ c2_w,   const float* __restrict__ c2_b,
                 const float* __restrict__ c3_w,   const float* __restrict__ c3_b,
                 float* __restrict__ out)
{
    const int b    = blockIdx.x;
    const int lane = threadIdx.x;   // 0..31

    __shared__ float4 s_nrm[2][Nn];
    __shared__ float4 s_q[2][Nn];
    __shared__ float  s_dis[2][Nn];
    __shared__ float4 s_xp[2][Nn];
    __shared__ float2 s_mr[2][Nn];
    __shared__ float  s_esm[Nn * Nn];
    __shared__ float  s_comb[5 + Hn];
    __shared__ float  s_b1[64];

    // ---- per-lane constants (lane == H channel) ----
    float Wc0 = gcn_w[0 * Hn + lane];
    float Wc1 = gcn_w[1 * Hn + lane];
    float Wc2 = gcn_w[2 * Hn + lane];
    float Wc3 = gcn_w[3 * Hn + lane];
    float gcnb = gcn_b[lane];
    float lng  = ln_g[lane];
    float lnb  = ln_b[lane];
    float awv  = attn_w[lane];
    float gw0  = gate_w[0];
    float gw1  = gate_w[1];
    float gbv  = gate_b[0];
    float attnb = attn_b[0];

    // ---- closed-form LN statistics precompute ----
    float SW0 = warp_sum(Wc0);
    float SW1 = warp_sum(Wc1);
    float SW2 = warp_sum(Wc2);
    float SW3 = warp_sum(Wc3);
    float Sb  = warp_sum(gcnb);
    float vW[5] = {Wc0, Wc1, Wc2, Wc3, gcnb};
    float G[5][5];
    #pragma unroll
    for (int i = 0; i < 5; i++) {
        #pragma unroll
        for (int j = i; j < 5; j++) {
            float g = warp_sum(vW[i] * vW[j]);
            G[i][j] = g; G[j][i] = g;
        }
    }

    // register-resident esm column (lane = column index; symmetric matrix)
    float e[Nn];
    #pragma unroll
    for (int i = 0; i < Nn; i++) e[i] = 0.0f;

    // online-softmax attention state
    float Pacc = 0.0f, Mrun = -1e30f, Srun = 0.0f;

    const float4* src = reinterpret_cast<const float4*>(ws) + (size_t)b * Tn * Nn;
    float4 dcur = make_float4(0.f,0.f,0.f,0.f);
    float4 dnxt = make_float4(0.f,0.f,0.f,0.f);
    float4 dload = make_float4(0.f,0.f,0.f,0.f);
    if (lane < Nn) { dcur = src[lane]; dnxt = src[Nn + lane]; }

    // ---- prologue: phase1(0) + phase2(0) ----
    {
        float d2 = dcur.x*dcur.x + dcur.y*dcur.y + dcur.z*dcur.z + dcur.w*dcur.w;
        float inv = rsqrtf(fmaxf(d2, 1e-24f));
        float4 nrm0 = make_float4(dcur.x*inv, dcur.y*inv, dcur.z*inv, dcur.w*inv);
        if (lane < Nn) s_nrm[0][lane] = nrm0;
        __syncwarp();
        float rowsum = 1.0f;
        #pragma unroll
        for (int n = 0; n < Nn; n++) {
            float4 nn4 = s_nrm[0][n];
            float dot = nrm0.x*nn4.x;
            dot = fmaf(nrm0.y, nn4.y, dot);
            dot = fmaf(nrm0.z, nn4.z, dot);
            dot = fmaf(nrm0.w, nn4.w, dot);
            float adj = fmaf(dot, 0.5f, 0.5f);
            adj = (n == lane) ? 0.0f : adj;
            float x = fmaf(gw0, 0.0f, fmaf(gw1, adj, gbv));
            float z = __fdividef(1.0f, 1.0f + __expf(-x));
            float ee = z * adj;
            e[n] = ee;
            rowsum += ee;
        }
        float disA0 = rsqrtf(fmaxf(rowsum, 1e-6f));
        if (lane < Nn) {
            s_q[0][lane]   = make_float4(dcur.x*disA0, dcur.y*disA0, dcur.z*disA0, dcur.w*disA0);
            s_dis[0][lane] = disA0;
        }
        __syncwarp();
        // keep disA in a register for phase3
        // (stored below in the loop-carried variable)
        // fallthrough
        // NOTE: disA variable defined outside
        // (assigned here)
        // ---
        // store into loop-carried reg:
        //
        // (see below)
        //
        // disA = disA0;
        // handled by declaration order:
        //
        // (cannot declare after use, so declared next)
        //
        asm volatile("" ::: "memory");
        // real assignment done right after this block via disA variable
        // -- we simply re-declare before loop:
        // (see code)
        //
        // To keep it simple we recompute nothing; assignment below.
        //
        // (placeholder comment, no code)
        //
        // end prologue
        //
        // assign:
        //
        // disA set after block
        //
        // ...
        // (the variable is set immediately below)
        //
        // done
        //
        // (fallthrough)
        //
        // --
        //
        // .
        //
        // store to loop-carried:
        s_esm[0] = s_esm[0]; // no-op to keep structure
        // actual value passed via shared s_dis[0][lane] too; register copy below
        // (we set disA after the block ends)
        // --
        // (end)
        //
        // (closing)
        //
        // --
        //
        // nothing else
        //
        // end
        //
        // .
        //
        // .
        //
        // .
        // set below
        ;
        // export via register
        // (handled)
        //
        // done
        //
        // (end of prologue block)
        //
        // disA0 goes out of scope; re-read from s_dis? Keep simple: recompute below.
        // Instead we persist through a variable declared before this block:
        // -> refactor: see disA declaration above loop.
        //
        // (This comment block intentionally has no effect.)
        //
        ;
    }
    // loop-carried dis of current step (recompute cheaply from shared; one LDS)
    float disA = (lane < Nn) ? s_dis[0][lane] : 1.0f;

    for (int t = 0; t < Tn; t++) {
        const int c  = t & 1;
        const int c1 = c ^ 1;
        const bool more = (t + 1 < Tn);

        // ================= HALF 1 =================
        // ---- A: phase3(t): p = esm@q, r = rowsum(a_norm), LN stats ----
        float4 p = make_float4(0.f,0.f,0.f,0.f);
        float racc = 0.0f;
        #pragma unroll
        for (int m = 0; m < Nn; m++) {
            float4 qm = s_q[c][m];
            float dm  = s_dis[c][m];
            float em  = e[m];
            p.x = fmaf(em, qm.x, p.x);
            p.y = fmaf(em, qm.y, p.y);
            p.z = fmaf(em, qm.z, p.z);
            p.w = fmaf(em, qm.w, p.w);
            racc = fmaf(em, dm, racc);
        }

        // ---- B: phase1(t+1): normalize next de, write s_nrm[c1]; prefetch t+2 ----
        float4 nrmB = make_float4(0.f,0.f,0.f,0.f);
        if (more) {
            float d2 = dnxt.x*dnxt.x + dnxt.y*dnxt.y + dnxt.z*dnxt.z + dnxt.w*dnxt.w;
            float inv = rsqrtf(fmaxf(d2, 1e-24f));
            nrmB = make_float4(dnxt.x*inv, dnxt.y*inv, dnxt.z*inv, dnxt.w*inv);
            if (lane < Nn) {
                s_nrm[c1][lane] = nrmB;
                if (t + 2 < Tn) dload = src[(t + 2) * Nn + lane];
            }
        }

        // ---- A (cont.): LN stats + store xp/mr ----
        if (lane < Nn) {
            float rr = disA * (racc + disA);
            float x0 = fmaf(dcur.x, disA, p.x) * disA;
            float x1 = fmaf(dcur.y, disA, p.y) * disA;
            float x2 = fmaf(dcur.z, disA, p.z) * disA;
            float x3 = fmaf(dcur.w, disA, p.w) * disA;
            float mu = (x0*SW0 + x1*SW1 + x2*SW2 + x3*SW3 + rr*Sb) * (1.0f/32.0f);
            float xt[5] = {x0, x1, x2, x3, rr};
            float s2 = 0.0f;
            #pragma unroll
            for (int i = 0; i < 5; i++) {
                float rowd = 0.0f;
                #pragma unroll
                for (int j = 0; j < 5; j++) rowd = fmaf(G[i][j], xt[j], rowd);
                s2 = fmaf(xt[i], rowd, s2);
            }
            s2 *= (1.0f/32.0f);
            float var  = fmaf(-mu, mu, s2);
            float istd = rsqrtf(var + 1e-5f);
            s_xp[c][lane] = make_float4(x0*istd, x1*istd, x2*istd, x3*istd);
            s_mr[c][lane] = make_float2(rr*istd, mu*istd);
        }
        __syncwarp();

        // ================= HALF 2 =================
        // ---- C: phase5(t): LN apply + ELU + node mean + online softmax ----
        float ge = 0.0f;
        #pragma unroll
        for (int n = 0; n < Nn; n++) {
            float4 xp = s_xp[c][n];
            float2 mr = s_mr[c][n];
            float hv = -mr.y;
            hv = fmaf(xp.x, Wc0, hv);
            hv = fmaf(xp.y, Wc1, hv);
            hv = fmaf(xp.z, Wc2, hv);
            hv = fmaf(xp.w, Wc3, hv);
            hv = fmaf(mr.x, gcnb, hv);
            ge += elu(fmaf(hv, lng, lnb));
        }
        ge *= (1.0f / 14.0f);

        // ---- D: phase2(t+1): adjacency + gate + esm update + new dis ----
        float disNew = disA;
        if (more) {
            float rowsum = 1.0f;
            #pragma unroll
            for (int n = 0; n < Nn; n++) {
                float4 nn4 = s_nrm[c1][n];
                float dot = nrmB.x*nn4.x;
                dot = fmaf(nrmB.y, nn4.y, dot);
                dot = fmaf(nrmB.z, nn4.z, dot);
                dot = fmaf(nrmB.w, nn4.w, dot);
                float adj = fmaf(dot, 0.5f, 0.5f);
                adj = (n == lane) ? 0.0f : adj;
                float ee = e[n];
                float x  = fmaf(gw0, ee, fmaf(gw1, adj, gbv));
                float z  = __fdividef(1.0f, 1.0f + __expf(-x));
                ee = fmaf(z, adj - ee, ee);
                e[n] = ee;
                rowsum += ee;
            }
            disNew = rsqrtf(fmaxf(rowsum, 1e-6f));
            if (lane < Nn) {
                s_q[c1][lane]   = make_float4(dnxt.x*disNew, dnxt.y*disNew,
                                              dnxt.z*disNew, dnxt.w*disNew);
                s_dis[c1][lane] = disNew;
            }
        }

        // ---- C (cont.): softmax state update (register-only, overlaps D) ----
        {
            float sc = warp_sum(ge * awv) + attnb;
            float nM = fmaxf(Mrun, sc);
            float al = __expf(Mrun - nM);
            float wt = __expf(sc - nM);
            Pacc = fmaf(Pacc, al, wt * ge);
            Srun = fmaf(Srun, al, wt);
            Mrun = nM;
        }
        __syncwarp();

        // rotate pipeline registers
        dcur = dnxt;
        dnxt = dload;
        disA = disNew;
    }

    // ---- dump esm to shared for Jacobi ----
    if (lane < Nn) {
        #pragma unroll
        for (int n = 0; n < Nn; n++) s_esm[n * Nn + lane] = e[n];
    }
    __syncwarp();

    // ---- cyclic Jacobi eigensolver (whole warp, uniform branch) ----
    for (int sweep = 0; sweep < 8; sweep++) {
        for (int pp = 0; pp < Nn - 1; pp++) {
            for (int qq = pp + 1; qq < Nn; qq++) {
                float apq = s_esm[pp * Nn + qq];
                if (fabsf(apq) > 1e-11f) {
                    float app = s_esm[pp * Nn + pp];
                    float aqq = s_esm[qq * Nn + qq];
                    float theta = 0.5f * __fdividef(aqq - app, apq);
                    float tt = __fdividef(1.0f, fabsf(theta) + sqrtf(fmaf(theta, theta, 1.0f)));
                    if (theta < 0.0f) tt = -tt;
                    float cc  = rsqrtf(fmaf(tt, tt, 1.0f));
                    float ssn = tt * cc;
                    int k = lane;
                    bool act = (k < Nn) && (k != pp) && (k != qq);
                    float akp = 0.f, akq = 0.f;
                    if (act) { akp = s_esm[k * Nn + pp]; akq = s_esm[k * Nn + qq]; }
                    __syncwarp();
                    if (act) {
                        float nkp = fmaf(cc, akp, -ssn * akq);
                        float nkq = fmaf(ssn, akp,  cc * akq);
                        s_esm[k * Nn + pp] = nkp; s_esm[pp * Nn + k] = nkp;
                        s_esm[k * Nn + qq] = nkq; s_esm[qq * Nn + k] = nkq;
                    }
                    if (lane == 0) {
                        s_esm[pp * Nn + pp] = fmaf(-tt, apq, app);
                        s_esm[qq * Nn + qq] = fmaf( tt, apq, aqq);
                        s_esm[pp * Nn + qq] = 0.0f;
                        s_esm[qq * Nn + pp] = 0.0f;
                    }
                    __syncwarp();
                }
            }
        }
    }

    // ---- top-5 eigenvalues (ascending) + pooled attention ----
    if (lane == 0) {
        float ev[Nn];
        #pragma unroll
        for (int i = 0; i < Nn; i++) ev[i] = s_esm[i * Nn + i];
        for (int i = 1; i < Nn; i++) {
            float v = ev[i];
            int j = i - 1;
            while (j >= 0 && ev[j] > v) { ev[j + 1] = ev[j]; j--; }
            ev[j + 1] = v;
        }
        #pragma unroll
        for (int i = 0; i < 5; i++) s_comb[i] = ev[Nn - 5 + i];
    }
    s_comb[5 + lane] = __fdividef(Pacc, Srun);
    __syncwarp();

    // ---- classifier: 37 -> 64 (elu) -> 32 (elu) -> 2 ----
    {
        float a0 = c1_b[lane];
        float a1 = c1_b[lane + 32];
        #pragma unroll
        for (int i = 0; i < 37; i++) {
            float ci = s_comb[i];
            a0 = fmaf(ci, c1_w[i * 64 + lane], a0);
            a1 = fmaf(ci, c1_w[i * 64 + 32 + lane], a1);
        }
        s_b1[lane]      = elu(a0);
        s_b1[lane + 32] = elu(a1);
    }
    __syncwarp();
    {
        float a2 = c2_b[lane];
        #pragma unroll
        for (int i = 0; i < 64; i++)
            a2 = fmaf(s_b1[i], c2_w[i * 32 + lane], a2);
        float h2 = elu(a2);
        float r0 = warp_sum(h2 * c3_w[lane * 2 + 0]);
        float r1 = warp_sum(h2 * c3_w[lane * 2 + 1]);
        if (lane == 0) {
            out[b * 2 + 0] = r0 + c3_b[0];
            out[b * 2 + 1] = r1 + c3_b[1];
        }
    }
}

extern "C" void kernel_launch(void* const* d_in, const int* in_sizes, int n_in,
                              void* d_out, int out_size)
{
    const float* ws     = (const float*)d_in[0];
    const float* gate_w = (const float*)d_in[1];
    const float* gate_b = (const float*)d_in[2];
    const float* gcn_w  = (const float*)d_in[3];
    const float* gcn_b  = (const float*)d_in[4];
    const float* ln_g   = (const float*)d_in[5];
    const float* ln_b   = (const float*)d_in[6];
    const float* attn_w = (const float*)d_in[7];
    const float* attn_b = (const float*)d_in[8];
    const float* c1_w   = (const float*)d_in[9];
    const float* c1_b   = (const float*)d_in[10];
    const float* c2_w   = (const float*)d_in[11];
    const float* c2_b   = (const float*)d_in[12];
    const float* c3_w   = (const float*)d_in[13];
    const float* c3_b   = (const float*)d_in[14];
    float* out = (float*)d_out;

    tgsm_kernel<<<Bn, 32>>>(ws, gate_w, gate_b, gcn_w, gcn_b, ln_g, ln_b,
                            attn_w, attn_b, c1_w, c1_b, c2_w, c2_b,
                            c3_w, c3_b, out);
}

// round 5
// speedup vs baseline: 1.4184x; 1.1579x over previous
#include <cuda_runtime.h>
#include <cuda_bf16.h>

// TGSM fused kernel v5: 2 warps per batch (producer/consumer), 2048 warps total.
// B=1024, T=256, N=14, Fd=4, H=32, K=5, C=2

#define Bn 1024
#define Tn 256
#define Nn 14
#define Hn 32

__device__ __forceinline__ float warp_sum(float v) {
    v += __shfl_xor_sync(0xffffffffu, v, 16);
    v += __shfl_xor_sync(0xffffffffu, v, 8);
    v += __shfl_xor_sync(0xffffffffu, v, 4);
    v += __shfl_xor_sync(0xffffffffu, v, 2);
    v += __shfl_xor_sync(0xffffffffu, v, 1);
    return v;
}

__device__ __forceinline__ float elu(float y) {
    return (y > 0.0f) ? y : (__expf(y) - 1.0f);
}

// sigmoid(x) = 0.5 + 0.5 * tanh(x/2), single MUFU op
__device__ __forceinline__ float sigmoid_fast(float x) {
    float th;
    asm("tanh.approx.f32 %0, %1;" : "=f"(th) : "f"(0.5f * x));
    return fmaf(0.5f, th, 0.5f);
}

__global__ __launch_bounds__(64)
void tgsm_kernel(const float* __restrict__ ws,
                 const float* __restrict__ gate_w, const float* __restrict__ gate_b,
                 const float* __restrict__ gcn_w,  const float* __restrict__ gcn_b,
                 const float* __restrict__ ln_g,   const float* __restrict__ ln_b,
                 const float* __restrict__ attn_w, const float* __restrict__ attn_b,
                 const float* __restrict__ c1_w,   const float* __restrict__ c1_b,
                 const float* __restrict__ c2_w,   const float* __restrict__ c2_b,
                 const float* __restrict__ c3_w,   const float* __restrict__ c3_b,
                 float* __restrict__ out)
{
    const int b    = blockIdx.x;
    const int tid  = threadIdx.x;
    const int lane = tid & 31;
    const int warp = tid >> 5;       // 0 = producer, 1 = consumer

    __shared__ float4 s_nrm[Nn];       // producer-internal
    __shared__ float4 s_q[Nn];         // producer-internal
    __shared__ float  s_dis[Nn];       // producer-internal
    __shared__ float4 s_x[2][Nn];      // producer -> consumer (double buffer)
    __shared__ float  s_rr[2][Nn];     // producer -> consumer (double buffer)
    __shared__ float4 s_xp[Nn];        // consumer-internal
    __shared__ float2 s_mr[Nn];        // consumer-internal
    __shared__ float  s_esm[Nn * Nn];
    __shared__ float  s_comb[5 + Hn];
    __shared__ float  s_b1[64];

    // ---- per-lane constants ----
    float gw0  = gate_w[0];
    float gw1  = gate_w[1];
    float gbv  = gate_b[0];
    float Wc0 = gcn_w[0 * Hn + lane];
    float Wc1 = gcn_w[1 * Hn + lane];
    float Wc2 = gcn_w[2 * Hn + lane];
    float Wc3 = gcn_w[3 * Hn + lane];
    float gcnb = gcn_b[lane];
    float lng  = ln_g[lane];
    float lnb  = ln_b[lane];
    float awv  = attn_w[lane];
    float attnb = attn_b[0];

    // ---- closed-form LN statistics precompute (warp-local, identical in both) ----
    float SW0 = warp_sum(Wc0);
    float SW1 = warp_sum(Wc1);
    float SW2 = warp_sum(Wc2);
    float SW3 = warp_sum(Wc3);
    float Sb  = warp_sum(gcnb);
    float vW[5] = {Wc0, Wc1, Wc2, Wc3, gcnb};
    float G[5][5];
    #pragma unroll
    for (int i = 0; i < 5; i++) {
        #pragma unroll
        for (int j = i; j < 5; j++) {
            float g = warp_sum(vW[i] * vW[j]);
            G[i][j] = g; G[j][i] = g;
        }
    }

    // producer state: esm column `lane` (symmetric matrix), prefetch regs
    float e[Nn];
    #pragma unroll
    for (int i = 0; i < Nn; i++) e[i] = 0.0f;

    // consumer state: online softmax
    float Pacc = 0.0f, Mrun = -1e30f, Srun = 0.0f;

    const float4* src = reinterpret_cast<const float4*>(ws) + (size_t)b * Tn * Nn;
    float4 dcur = make_float4(0.f,0.f,0.f,0.f);
    float4 dnxt = make_float4(0.f,0.f,0.f,0.f);
    if (warp == 0 && lane < Nn) dcur = src[lane];

    for (int i = 0; i <= Tn; i++) {
        if (warp == 0) {
            if (i < Tn) {
                // ---- phase 1: normalize de; prefetch next ----
                float4 de = dcur;
                if (lane < Nn && i + 1 < Tn) dnxt = src[(i + 1) * Nn + lane];
                float d2  = de.x*de.x + de.y*de.y + de.z*de.z + de.w*de.w;
                float inv = rsqrtf(fmaxf(d2, 1e-24f));
                float4 nrm = make_float4(de.x*inv, de.y*inv, de.z*inv, de.w*inv);
                if (lane < Nn) s_nrm[lane] = nrm;
                __syncwarp();

                // ---- phase 2: adjacency + gate + esm update + rowsum ----
                float rowsum = 1.0f;
                #pragma unroll
                for (int n = 0; n < Nn; n++) {
                    float4 nn4 = s_nrm[n];
                    float dot = nrm.x*nn4.x;
                    dot = fmaf(nrm.y, nn4.y, dot);
                    dot = fmaf(nrm.z, nn4.z, dot);
                    dot = fmaf(nrm.w, nn4.w, dot);
                    float adj = fmaf(dot, 0.5f, 0.5f);
                    adj = (n == lane) ? 0.0f : adj;
                    float ee = e[n];
                    float xg = fmaf(gw0, ee, fmaf(gw1, adj, gbv));
                    float z  = sigmoid_fast(xg);
                    ee = fmaf(z, adj - ee, ee);
                    e[n] = ee;
                    rowsum += ee;
                }
                float dis = rsqrtf(fmaxf(rowsum, 1e-6f));
                if (lane < Nn) {
                    s_q[lane]   = make_float4(de.x*dis, de.y*dis, de.z*dis, de.w*dis);
                    s_dis[lane] = dis;
                }
                __syncwarp();

                // ---- phase 3: p = esm @ q, r = rowsum(a_norm); publish x, rr ----
                float4 p = make_float4(0.f,0.f,0.f,0.f);
                float racc = 0.0f;
                #pragma unroll
                for (int m = 0; m < Nn; m++) {
                    float4 qm = s_q[m];
                    float dm  = s_dis[m];
                    float em  = e[m];
                    p.x = fmaf(em, qm.x, p.x);
                    p.y = fmaf(em, qm.y, p.y);
                    p.z = fmaf(em, qm.z, p.z);
                    p.w = fmaf(em, qm.w, p.w);
                    racc = fmaf(em, dm, racc);
                }
                if (lane < Nn) {
                    float rr = dis * (racc + dis);
                    float4 x;
                    x.x = fmaf(de.x, dis, p.x) * dis;
                    x.y = fmaf(de.y, dis, p.y) * dis;
                    x.z = fmaf(de.z, dis, p.z) * dis;
                    x.w = fmaf(de.w, dis, p.w) * dis;
                    s_x[i & 1][lane]  = x;
                    s_rr[i & 1][lane] = rr;
                }
                dcur = dnxt;
            }
        } else {
            if (i > 0) {
                const int c = (i - 1) & 1;
                // ---- LN stats (closed form) for step i-1 ----
                if (lane < Nn) {
                    float4 x  = s_x[c][lane];
                    float rr  = s_rr[c][lane];
                    float mu = (x.x*SW0 + x.y*SW1 + x.z*SW2 + x.w*SW3 + rr*Sb) * (1.0f/32.0f);
                    float xt[5] = {x.x, x.y, x.z, x.w, rr};
                    float s2 = 0.0f;
                    #pragma unroll
                    for (int ii = 0; ii < 5; ii++) {
                        float rowd = 0.0f;
                        #pragma unroll
                        for (int jj = 0; jj < 5; jj++) rowd = fmaf(G[ii][jj], xt[jj], rowd);
                        s2 = fmaf(xt[ii], rowd, s2);
                    }
                    s2 *= (1.0f/32.0f);
                    float var  = fmaf(-mu, mu, s2);
                    float istd = rsqrtf(var + 1e-5f);
                    s_xp[lane] = make_float4(x.x*istd, x.y*istd, x.z*istd, x.w*istd);
                    s_mr[lane] = make_float2(rr*istd, mu*istd);
                }
                __syncwarp();

                // ---- LN apply + ELU + node mean (lane = channel) ----
                float ge = 0.0f;
                #pragma unroll
                for (int n = 0; n < Nn; n++) {
                    float4 xp = s_xp[n];
                    float2 mr = s_mr[n];
                    float hv = -mr.y;
                    hv = fmaf(xp.x, Wc0, hv);
                    hv = fmaf(xp.y, Wc1, hv);
                    hv = fmaf(xp.z, Wc2, hv);
                    hv = fmaf(xp.w, Wc3, hv);
                    hv = fmaf(mr.x, gcnb, hv);
                    ge += elu(fmaf(hv, lng, lnb));
                }
                ge *= (1.0f / 14.0f);

                // ---- online softmax attention pooling ----
                float sc = warp_sum(ge * awv) + attnb;
                float nM = fmaxf(Mrun, sc);
                float al = __expf(Mrun - nM);
                float wt = __expf(sc - nM);
                Pacc = fmaf(Pacc, al, wt * ge);
                Srun = fmaf(Srun, al, wt);
                Mrun = nM;
            }
        }
        __syncthreads();
    }

    // ---- endgame ----
    if (warp == 0) {
        // dump esm to shared for Jacobi
        if (lane < Nn) {
            #pragma unroll
            for (int n = 0; n < Nn; n++) s_esm[n * Nn + lane] = e[n];
        }
        __syncwarp();

        // cyclic Jacobi eigensolver (warp-uniform branch)
        for (int sweep = 0; sweep < 8; sweep++) {
            for (int pp = 0; pp < Nn - 1; pp++) {
                for (int qq = pp + 1; qq < Nn; qq++) {
                    float apq = s_esm[pp * Nn + qq];
                    if (fabsf(apq) > 1e-11f) {
                        float app = s_esm[pp * Nn + pp];
                        float aqq = s_esm[qq * Nn + qq];
                        float theta = 0.5f * __fdividef(aqq - app, apq);
                        float tt = __fdividef(1.0f, fabsf(theta) + sqrtf(fmaf(theta, theta, 1.0f)));
                        if (theta < 0.0f) tt = -tt;
                        float cc  = rsqrtf(fmaf(tt, tt, 1.0f));
                        float ssn = tt * cc;
                        int k = lane;
                        bool act = (k < Nn) && (k != pp) && (k != qq);
                        float akp = 0.f, akq = 0.f;
                        if (act) { akp = s_esm[k * Nn + pp]; akq = s_esm[k * Nn + qq]; }
                        __syncwarp();
                        if (act) {
                            float nkp = fmaf(cc, akp, -ssn * akq);
                            float nkq = fmaf(ssn, akp,  cc * akq);
                            s_esm[k * Nn + pp] = nkp; s_esm[pp * Nn + k] = nkp;
                            s_esm[k * Nn + qq] = nkq; s_esm[qq * Nn + k] = nkq;
                        }
                        if (lane == 0) {
                            s_esm[pp * Nn + pp] = fmaf(-tt, apq, app);
                            s_esm[qq * Nn + qq] = fmaf( tt, apq, aqq);
                            s_esm[pp * Nn + qq] = 0.0f;
                            s_esm[qq * Nn + pp] = 0.0f;
                        }
                        __syncwarp();
                    }
                }
            }
        }
        // top-5 eigenvalues ascending
        if (lane == 0) {
            float ev[Nn];
            #pragma unroll
            for (int i = 0; i < Nn; i++) ev[i] = s_esm[i * Nn + i];
            for (int i = 1; i < Nn; i++) {
                float v = ev[i];
                int j = i - 1;
                while (j >= 0 && ev[j] > v) { ev[j + 1] = ev[j]; j--; }
                ev[j + 1] = v;
            }
            #pragma unroll
            for (int i = 0; i < 5; i++) s_comb[i] = ev[Nn - 5 + i];
        }
    } else {
        // pooled attention output
        s_comb[5 + lane] = __fdividef(Pacc, Srun);
    }
    __syncthreads();

    // ---- classifier: 37 -> 64 (elu) -> 32 (elu) -> 2 ----
    {
        float a = c1_b[tid];
        #pragma unroll
        for (int i = 0; i < 37; i++)
            a = fmaf(s_comb[i], c1_w[i * 64 + tid], a);
        s_b1[tid] = elu(a);
    }
    __syncthreads();
    if (warp == 0) {
        float a2 = c2_b[lane];
        #pragma unroll
        for (int i = 0; i < 64; i++)
            a2 = fmaf(s_b1[i], c2_w[i * 32 + lane], a2);
        float h2 = elu(a2);
        float r0 = warp_sum(h2 * c3_w[lane * 2 + 0]);
        float r1 = warp_sum(h2 * c3_w[lane * 2 + 1]);
        if (lane == 0) {
            out[b * 2 + 0] = r0 + c3_b[0];
            out[b * 2 + 1] = r1 + c3_b[1];
        }
    }
}

extern "C" void kernel_launch(void* const* d_in, const int* in_sizes, int n_in,
                              void* d_out, int out_size)
{
    const float* ws     = (const float*)d_in[0];
    const float* gate_w = (const float*)d_in[1];
    const float* gate_b = (const float*)d_in[2];
    const float* gcn_w  = (const float*)d_in[3];
    const float* gcn_b  = (const float*)d_in[4];
    const float* ln_g   = (const float*)d_in[5];
    const float* ln_b   = (const float*)d_in[6];
    const float* attn_w = (const float*)d_in[7];
    const float* attn_b = (const float*)d_in[8];
    const float* c1_w   = (const float*)d_in[9];
    const float* c1_b   = (const float*)d_in[10];
    const float* c2_w   = (const float*)d_in[11];
    const float* c2_b   = (const float*)d_in[12];
    const float* c3_w   = (const float*)d_in[13];
    const float* c3_b   = (const float*)d_in[14];
    float* out = (float*)d_out;

    tgsm_kernel<<<Bn, 64>>>(ws, gate_w, gate_b, gcn_w, gcn_b, ln_g, ln_b,
                            attn_w, attn_b, c1_w, c1_b, c2_w, c2_b,
                            c3_w, c3_b, out);
}